// round 1
// baseline (speedup 1.0000x reference)
#include <cuda_runtime.h>
#include <cuda_bf16.h>
#include <math.h>

// Volume: D=64, H=128, W=128 ; B=2, C=4  (fixed shapes for this problem)
#define DZ 64
#define HY 128
#define WX 128
#define NVOX (DZ * HY * WX)   // 1,048,576
#define NMASK 12              // 6 pred masks + 6 target masks
#define NPROB 36              // 12 mask-CC + 12 eroded-CC + 12 background-CC

// Scratch (device globals: no allocation allowed in kernel_launch)
__device__ unsigned char g_mask[NMASK * NVOX];   // 12 MB
__device__ unsigned char g_er[NMASK * NVOX];     // 12 MB
__device__ unsigned char g_reach[NMASK * NVOX];  // 12 MB (border-reachability flag per bg root)
__device__ int           g_L[NPROB * NVOX];      // 144 MB union-find labels
__device__ int           g_cnt[NPROB];           // [0..11]=b0, [12..23]=b0e, [24..35]=cavity

// ---------------- union-find ----------------
__device__ __forceinline__ int uf_find(int* L, int x) {
    while (true) {
        int p = L[x];
        if (p == x) return x;
        int gp = L[p];
        if (gp != p) L[x] = gp;   // path halving (safe concurrently)
        x = gp;
    }
}

__device__ __forceinline__ void uf_union(int* L, int a, int b) {
    while (true) {
        a = uf_find(L, a);
        b = uf_find(L, b);
        if (a == b) return;
        if (a > b) { int t = a; a = b; b = t; }
        int old = atomicMin(&L[b], a);
        if (old == b) return;
        b = old;
    }
}

// ---------------- kernels ----------------

__global__ void k_zero_counters() {
    int i = threadIdx.x;
    if (i < NPROB) g_cnt[i] = 0;
}

// Build 6 pred masks (softmax prob > 0.5, classes 1..3) and 6 target masks.
// grid: (NVOX/256, B)
__global__ void k_masks(const float* __restrict__ pred, const int* __restrict__ target) {
    int v = blockIdx.x * blockDim.x + threadIdx.x;
    int b = blockIdx.y;
    const float* pp = pred + ((size_t)b * 4) * NVOX + v;
    float x0 = pp[0];
    float x1 = pp[NVOX];
    float x2 = pp[2 * NVOX];
    float x3 = pp[3 * NVOX];
    float m = fmaxf(fmaxf(x0, x1), fmaxf(x2, x3));
    float e0 = expf(x0 - m), e1 = expf(x1 - m), e2 = expf(x2 - m), e3 = expf(x3 - m);
    float half_s = 0.5f * (e0 + e1 + e2 + e3);
    g_mask[(b * 3 + 0) * NVOX + v] = (e1 > half_s);
    g_mask[(b * 3 + 1) * NVOX + v] = (e2 > half_s);
    g_mask[(b * 3 + 2) * NVOX + v] = (e3 > half_s);
    int t = target[(size_t)b * NVOX + v];
    g_mask[(6 + b * 3 + 0) * NVOX + v] = (t == 1);
    g_mask[(6 + b * 3 + 1) * NVOX + v] = (t == 2);
    g_mask[(6 + b * 3 + 2) * NVOX + v] = (t == 3);
}

// Erosion (6-neighborhood, border -> false).  grid: (NVOX/256, 12)
__global__ void k_erode() {
    int v = blockIdx.x * blockDim.x + threadIdx.x;
    int p = blockIdx.y;
    const unsigned char* M = g_mask + (size_t)p * NVOX;
    unsigned char e = M[v];
    if (e) {
        int x = v & (WX - 1);
        int y = (v >> 7) & (HY - 1);
        int z = v >> 14;
        bool inner = (x > 0) && (x < WX - 1) && (y > 0) && (y < HY - 1) && (z > 0) && (z < DZ - 1);
        e = inner && M[v - 1] && M[v + 1] && M[v - WX] && M[v + WX] &&
            M[v - HY * WX] && M[v + HY * WX];
    }
    g_er[(size_t)p * NVOX + v] = e;
}

// Init labels for 36 problems; zero reach flags for bg problems.
// grid: (NVOX/256, 36)
__global__ void k_init() {
    int v = blockIdx.x * blockDim.x + threadIdx.x;
    int p = blockIdx.y;
    unsigned char occ;
    if (p < 12) {
        occ = g_mask[(size_t)p * NVOX + v];
    } else if (p < 24) {
        occ = g_er[(size_t)(p - 12) * NVOX + v];
    } else {
        occ = !g_mask[(size_t)(p - 24) * NVOX + v];
        g_reach[(size_t)(p - 24) * NVOX + v] = 0;
    }
    g_L[(size_t)p * NVOX + v] = occ ? v : -1;
}

// Merge: union with -x, -y, -z neighbors.  grid: (NVOX/256, 36)
__global__ void k_merge() {
    int v = blockIdx.x * blockDim.x + threadIdx.x;
    int p = blockIdx.y;
    int* L = g_L + (size_t)p * NVOX;
    if (L[v] < 0) return;
    int x = v & (WX - 1);
    int y = (v >> 7) & (HY - 1);
    int z = v >> 14;
    if (x > 0 && L[v - 1] >= 0)       uf_union(L, v, v - 1);
    if (y > 0 && L[v - WX] >= 0)      uf_union(L, v, v - WX);
    if (z > 0 && L[v - HY * WX] >= 0) uf_union(L, v, v - HY * WX);
}

// Flatten labels to roots.  grid: (NVOX/256, 36)
__global__ void k_flatten() {
    int v = blockIdx.x * blockDim.x + threadIdx.x;
    int p = blockIdx.y;
    int* L = g_L + (size_t)p * NVOX;
    if (L[v] >= 0) L[v] = uf_find(L, v);
}

// Mark bg components touching the volume border.  grid: (NVOX/256, 12)
__global__ void k_border() {
    int v = blockIdx.x * blockDim.x + threadIdx.x;
    int p = blockIdx.y;            // bg problem index 0..11  (global problem 24+p)
    int x = v & (WX - 1);
    int y = (v >> 7) & (HY - 1);
    int z = v >> 14;
    bool border = (x == 0) || (x == WX - 1) || (y == 0) || (y == HY - 1) ||
                  (z == 0) || (z == DZ - 1);
    if (!border) return;
    int root = g_L[(size_t)(24 + p) * NVOX + v];   // already flattened
    if (root >= 0) g_reach[(size_t)p * NVOX + root] = 1;
}

// Count roots (b0, b0e) and cavity voxels.  grid: (NVOX/256, 36)
__global__ void k_count() {
    int v = blockIdx.x * blockDim.x + threadIdx.x;
    int p = blockIdx.y;
    int Lv = g_L[(size_t)p * NVOX + v];
    int c = 0;
    if (Lv >= 0) {
        if (p < 24) {
            c = (Lv == v) ? 1 : 0;
        } else {
            c = (g_reach[(size_t)(p - 24) * NVOX + Lv] == 0) ? 1 : 0;
        }
    }
    // reduce within warp, then block, then one atomic per block
    #pragma unroll
    for (int off = 16; off > 0; off >>= 1)
        c += __shfl_down_sync(0xFFFFFFFFu, c, off);
    __shared__ int ssum;
    if (threadIdx.x == 0) ssum = 0;
    __syncthreads();
    if ((threadIdx.x & 31) == 0 && c) atomicAdd(&ssum, c);
    __syncthreads();
    if (threadIdx.x == 0 && ssum) atomicAdd(&g_cnt[p], ssum);
}

__device__ __forceinline__ int iabs_(int a) { return a < 0 ? -a : a; }
__device__ __forceinline__ int imax0_(int a) { return a > 0 ? a : 0; }

__global__ void k_final(float* __restrict__ out) {
    float tot = 0.0f;
    #pragma unroll
    for (int i = 0; i < 6; i++) {
        int pb0 = g_cnt[i],       tb0 = g_cnt[i + 6];
        int pbe = g_cnt[12 + i],  tbe = g_cnt[12 + i + 6];
        int pcv = g_cnt[24 + i],  tcv = g_cnt[24 + i + 6];
        int pb1 = imax0_(pb0 - pbe), tb1 = imax0_(tb0 - tbe);
        int pb2 = pcv / 100,         tb2 = tcv / 100;
        tot += (float)(iabs_(pb0 - tb0) + iabs_(pb1 - tb1) + iabs_(pb2 - tb2));
    }
    out[0] = 0.1f * tot / 6.0f;
}

// ---------------- launch ----------------
extern "C" void kernel_launch(void* const* d_in, const int* in_sizes, int n_in,
                              void* d_out, int out_size) {
    const float* pred   = (const float*)d_in[0];
    const int*   target = (const int*)d_in[1];
    float*       out    = (float*)d_out;

    const int T = 256;
    const int BX = NVOX / T;   // 4096

    k_zero_counters<<<1, 64>>>();
    k_masks<<<dim3(BX, 2), T>>>(pred, target);
    k_erode<<<dim3(BX, NMASK), T>>>();
    k_init<<<dim3(BX, NPROB), T>>>();
    k_merge<<<dim3(BX, NPROB), T>>>();
    k_flatten<<<dim3(BX, NPROB), T>>>();
    k_border<<<dim3(BX, NMASK), T>>>();
    k_count<<<dim3(BX, NPROB), T>>>();
    k_final<<<1, 1>>>(out);
}

// round 5
// speedup vs baseline: 2.6095x; 2.6095x over previous
#include <cuda_runtime.h>
#include <cuda_bf16.h>
#include <stdint.h>
#include <math.h>

// Volume: D=64, H=128, W=128 ; B=2, C=4  (fixed shapes)
#define DZ 64
#define HY 128
#define WX 128
#define HW (HY * WX)          // 16384
#define NVOX (DZ * HY * WX)   // 1,048,576
#define NMASK 12
#define NPROB 36

typedef unsigned int u32;
typedef unsigned char u8;

// Scratch (device globals)
__device__ u8  g_mask[NMASK * NVOX];   // 12 MB
__device__ u8  g_reach[NMASK * NVOX];  // 12 MB
__device__ int g_L[(size_t)NPROB * NVOX];  // 144 MB
__device__ int g_cnt[NPROB];

// ---------------- union-find ----------------
__device__ __forceinline__ int uf_find(int* L, int x) {
    while (true) {
        int p = L[x];
        if (p == x) return x;
        int gp = L[p];
        if (gp != p) L[x] = gp;   // path halving
        x = gp;
    }
}

__device__ __forceinline__ void uf_union(int* L, int a, int b) {
    while (true) {
        a = uf_find(L, a);
        b = uf_find(L, b);
        if (a == b) return;
        if (a > b) { int t = a; a = b; b = t; }
        int old = atomicMin(&L[b], a);
        if (old == b) return;
        b = old;
    }
}

// count of consecutive set bits strictly below position x in a 128-bit row bitmap
__device__ __forceinline__ int trailing_run(const u32* bits, int x) {
    int r = 0;
    int w = x >> 5, b = x & 31;
    if (b) {
        u32 below = bits[w] << (32 - b);   // top b bits = bits below x
        int ones = __clz(~below);
        if (ones < b) return ones;
        r = b;
    }
    for (int ww = w - 1; ww >= 0; --ww) {
        u32 word = bits[ww];
        if (word == 0xffffffffu) { r += 32; continue; }
        return r + __clz(~word);
    }
    return r;
}

// ---------------- kernels ----------------

__global__ void k_zero_counters() {
    int i = threadIdx.x;
    if (i < NPROB) g_cnt[i] = 0;
}

// Build 6 pred masks + 6 target masks, 4 voxels/thread.  grid:(NVOX/1024, 2)
__global__ void k_masks(const float* __restrict__ pred, const int* __restrict__ target) {
    int b = blockIdx.y;
    int vbase = (blockIdx.x * 256 + threadIdx.x) * 4;
    const float* pp = pred + (size_t)b * 4 * NVOX + vbase;
    float4 a0 = *(const float4*)(pp);
    float4 a1 = *(const float4*)(pp + NVOX);
    float4 a2 = *(const float4*)(pp + 2 * NVOX);
    float4 a3 = *(const float4*)(pp + 3 * NVOX);
    int4 t = *(const int4*)(target + (size_t)b * NVOX + vbase);

    u8 m1[4], m2[4], m3[4];
    float x0s[4] = {a0.x, a0.y, a0.z, a0.w};
    float x1s[4] = {a1.x, a1.y, a1.z, a1.w};
    float x2s[4] = {a2.x, a2.y, a2.z, a2.w};
    float x3s[4] = {a3.x, a3.y, a3.z, a3.w};
    #pragma unroll
    for (int i = 0; i < 4; i++) {
        float m = fmaxf(fmaxf(x0s[i], x1s[i]), fmaxf(x2s[i], x3s[i]));
        float e0 = expf(x0s[i] - m), e1 = expf(x1s[i] - m);
        float e2 = expf(x2s[i] - m), e3 = expf(x3s[i] - m);
        float h = 0.5f * (e0 + e1 + e2 + e3);
        m1[i] = e1 > h; m2[i] = e2 > h; m3[i] = e3 > h;
    }
    int ts[4] = {t.x, t.y, t.z, t.w};
    uchar4 u;
    u = make_uchar4(m1[0], m1[1], m1[2], m1[3]);
    *(uchar4*)(g_mask + (size_t)(b * 3 + 0) * NVOX + vbase) = u;
    u = make_uchar4(m2[0], m2[1], m2[2], m2[3]);
    *(uchar4*)(g_mask + (size_t)(b * 3 + 1) * NVOX + vbase) = u;
    u = make_uchar4(m3[0], m3[1], m3[2], m3[3]);
    *(uchar4*)(g_mask + (size_t)(b * 3 + 2) * NVOX + vbase) = u;
    u = make_uchar4(ts[0] == 1, ts[1] == 1, ts[2] == 1, ts[3] == 1);
    *(uchar4*)(g_mask + (size_t)(6 + b * 3 + 0) * NVOX + vbase) = u;
    u = make_uchar4(ts[0] == 2, ts[1] == 2, ts[2] == 2, ts[3] == 2);
    *(uchar4*)(g_mask + (size_t)(6 + b * 3 + 1) * NVOX + vbase) = u;
    u = make_uchar4(ts[0] == 3, ts[1] == 3, ts[2] == 3, ts[3] == 3);
    *(uchar4*)(g_mask + (size_t)(6 + b * 3 + 2) * NVOX + vbase) = u;
}

// Init labels with x-run-start labeling. 128 threads x 4 voxels = 4 rows/block.
// p<12: mask CC ; 12..23: eroded CC (erosion on the fly) ; 24..35: background CC
// grid:(NVOX/512, 36) block 128
__global__ void k_init() {
    __shared__ u32 rowbits[4][4];
    int tid = threadIdx.x;
    int p = blockIdx.y;
    int warp = tid >> 5, lane = tid & 31;
    int vbase = blockIdx.x * 512 + tid * 4;

    if (tid < 16) ((u32*)rowbits)[tid] = 0;
    __syncthreads();

    u8 occ[4];
    if (p < 12) {
        const u8* M = g_mask + (size_t)p * NVOX;
        uchar4 m4 = *(const uchar4*)(M + vbase);
        occ[0] = m4.x; occ[1] = m4.y; occ[2] = m4.z; occ[3] = m4.w;
    } else if (p < 24) {
        const u8* M = g_mask + (size_t)(p - 12) * NVOX;
        int x0 = vbase & (WX - 1);
        int y = (vbase >> 7) & (HY - 1);
        int z = vbase >> 14;
        bool yz_in = (y > 0) && (y < HY - 1) && (z > 0) && (z < DZ - 1);
        #pragma unroll
        for (int i = 0; i < 4; i++) {
            int v = vbase + i, x = x0 + i;
            u8 e = 0;
            if (yz_in && x > 0 && x < WX - 1 && M[v]) {
                e = M[v - 1] && M[v + 1] && M[v - WX] && M[v + WX] &&
                    M[v - HW] && M[v + HW];
            }
            occ[i] = e;
        }
    } else {
        const u8* M = g_mask + (size_t)(p - 24) * NVOX;
        uchar4 m4 = *(const uchar4*)(M + vbase);
        occ[0] = !m4.x; occ[1] = !m4.y; occ[2] = !m4.z; occ[3] = !m4.w;
        *(u32*)(g_reach + (size_t)(p - 24) * NVOX + vbase) = 0;
    }

    u32 nib = (occ[0] ? 1u : 0u) | (occ[1] ? 2u : 0u) |
              (occ[2] ? 4u : 0u) | (occ[3] ? 8u : 0u);
    int x0 = lane * 4;
    atomicOr(&rowbits[warp][x0 >> 5], nib << (x0 & 31));
    __syncwarp();

    int r = trailing_run(rowbits[warp], x0);
    int lb[4];
    #pragma unroll
    for (int i = 0; i < 4; i++) {
        if (occ[i]) { lb[i] = vbase + i - r; r++; }
        else        { lb[i] = -1; r = 0; }
    }
    *(int4*)(g_L + (size_t)p * NVOX + vbase) = make_int4(lb[0], lb[1], lb[2], lb[3]);
}

// Merge: only -y and -z unions needed (x merged by run labels).
// grid:(NVOX/1024, 36) block 256, 4 voxels/thread
__global__ void k_merge() {
    int p = blockIdx.y;
    int* L = g_L + (size_t)p * NVOX;
    int vbase = (blockIdx.x * 256 + threadIdx.x) * 4;
    int4 a4 = *(const int4*)(L + vbase);
    if (a4.x < 0 && a4.y < 0 && a4.z < 0 && a4.w < 0) return;
    int la[4] = {a4.x, a4.y, a4.z, a4.w};
    int y = (vbase >> 7) & (HY - 1);
    int z = vbase >> 14;
    if (y > 0) {
        int4 u4 = *(const int4*)(L + vbase - WX);
        int lu[4] = {u4.x, u4.y, u4.z, u4.w};
        int pa = -2, pu = -2;
        #pragma unroll
        for (int i = 0; i < 4; i++) {
            if (la[i] >= 0 && lu[i] >= 0 && (la[i] != pa || lu[i] != pu)) {
                uf_union(L, vbase + i, vbase + i - WX);
                pa = la[i]; pu = lu[i];
            }
        }
    }
    if (z > 0) {
        int4 u4 = *(const int4*)(L + vbase - HW);
        int lu[4] = {u4.x, u4.y, u4.z, u4.w};
        int pa = -2, pu = -2;
        #pragma unroll
        for (int i = 0; i < 4; i++) {
            if (la[i] >= 0 && lu[i] >= 0 && (la[i] != pa || lu[i] != pu)) {
                uf_union(L, vbase + i, vbase + i - HW);
                pa = la[i]; pu = lu[i];
            }
        }
    }
}

// Flatten labels to roots — ONLY the 12 background problems.
// grid:(NVOX/1024, 12) block 256
__global__ void k_flatten_bg() {
    int p = 24 + blockIdx.y;
    int* L = g_L + (size_t)p * NVOX;
    int vbase = (blockIdx.x * 256 + threadIdx.x) * 4;
    int4 a = *(const int4*)(L + vbase);
    if (a.x >= 0) a.x = uf_find(L, vbase);
    if (a.y >= 0) a.y = uf_find(L, vbase + 1);
    if (a.z >= 0) a.z = uf_find(L, vbase + 2);
    if (a.w >= 0) a.w = uf_find(L, vbase + 3);
    *(int4*)(L + vbase) = a;
}

// Mark bg components touching the volume border (labels already flat).
// grid:(NVOX/1024, 12) block 256 — interior threads do no memory work.
__global__ void k_border() {
    int p = blockIdx.y;
    int vbase = (blockIdx.x * 256 + threadIdx.x) * 4;
    int x0 = vbase & (WX - 1);
    int y = (vbase >> 7) & (HY - 1);
    int z = vbase >> 14;
    const int* L = g_L + (size_t)(24 + p) * NVOX;
    u8* R = g_reach + (size_t)p * NVOX;
    bool grpB = (z == 0) || (z == DZ - 1) || (y == 0) || (y == HY - 1);
    if (grpB) {
        #pragma unroll
        for (int i = 0; i < 4; i++) {
            int r = L[vbase + i];
            if (r >= 0) R[r] = 1;
        }
    } else if (x0 == 0) {
        int r = L[vbase];
        if (r >= 0) R[r] = 1;
    } else if (x0 == WX - 4) {
        int r = L[vbase + 3];
        if (r >= 0) R[r] = 1;
    }
}

// Count roots (p<24) / cavity voxels (p>=24).  grid:(NVOX/1024, 36) block 256
__global__ void k_count() {
    int p = blockIdx.y;
    int vbase = (blockIdx.x * 256 + threadIdx.x) * 4;
    const int* L = g_L + (size_t)p * NVOX;
    int4 a = *(const int4*)(L + vbase);
    int c = 0;
    if (p < 24) {
        c = (a.x == vbase) + (a.y == vbase + 1) + (a.z == vbase + 2) + (a.w == vbase + 3);
    } else {
        const u8* R = g_reach + (size_t)(p - 24) * NVOX;
        if (a.x >= 0) c += (R[a.x] == 0);
        if (a.y >= 0) c += (R[a.y] == 0);
        if (a.z >= 0) c += (R[a.z] == 0);
        if (a.w >= 0) c += (R[a.w] == 0);
    }
    #pragma unroll
    for (int off = 16; off > 0; off >>= 1)
        c += __shfl_down_sync(0xFFFFFFFFu, c, off);
    __shared__ int ssum;
    if (threadIdx.x == 0) ssum = 0;
    __syncthreads();
    if ((threadIdx.x & 31) == 0 && c) atomicAdd(&ssum, c);
    __syncthreads();
    if (threadIdx.x == 0 && ssum) atomicAdd(&g_cnt[p], ssum);
}

__device__ __forceinline__ int iabs_(int a) { return a < 0 ? -a : a; }
__device__ __forceinline__ int imax0_(int a) { return a > 0 ? a : 0; }

__global__ void k_final(float* __restrict__ out) {
    float tot = 0.0f;
    #pragma unroll
    for (int i = 0; i < 6; i++) {
        int pb0 = g_cnt[i],      tb0 = g_cnt[i + 6];
        int pbe = g_cnt[12 + i], tbe = g_cnt[12 + i + 6];
        int pcv = g_cnt[24 + i], tcv = g_cnt[24 + i + 6];
        int pb1 = imax0_(pb0 - pbe), tb1 = imax0_(tb0 - tbe);
        int pb2 = pcv / 100,         tb2 = tcv / 100;
        tot += (float)(iabs_(pb0 - tb0) + iabs_(pb1 - tb1) + iabs_(pb2 - tb2));
    }
    out[0] = 0.1f * tot / 6.0f;
}

// ---------------- launch ----------------
extern "C" void kernel_launch(void* const* d_in, const int* in_sizes, int n_in,
                              void* d_out, int out_size) {
    const float* pred   = (const float*)d_in[0];
    const int*   target = (const int*)d_in[1];
    float*       out    = (float*)d_out;

    k_zero_counters<<<1, 64>>>();
    k_masks<<<dim3(NVOX / 1024, 2), 256>>>(pred, target);
    k_init<<<dim3(NVOX / 512, NPROB), 128>>>();
    k_merge<<<dim3(NVOX / 1024, NPROB), 256>>>();
    k_flatten_bg<<<dim3(NVOX / 1024, 12), 256>>>();
    k_border<<<dim3(NVOX / 1024, 12), 256>>>();
    k_count<<<dim3(NVOX / 1024, NPROB), 256>>>();
    k_final<<<1, 1>>>(out);
}